// round 3
// baseline (speedup 1.0000x reference)
#include <cuda_runtime.h>

// ---------------------------------------------------------------------------
// FanoCoupling: out = x + scatter-add over 7 Fano lines of softmax-gated
// Linear(concat(x_i, x_j)).
//
// Reduction: W = [W1 | W2], each 64x64.  Only 8 unique half-matvecs needed:
//   A0=W1 x0, A1=W1 x1, A3=W1 x3, A4=W1 x4, B1=W2 x1, B2=W2 x2, B3=W2 x3, B5=W2 x5
// Combine:
//   out0=x0, out1=x1, out3=x3
//   out2 = x2 + g0*(A0+B1+b)
//   out4 = x4 + g1*(A0+B3+b)
//   out5 = x5 + g3*(A1+B3+b) + g6*(A4+B2+b)
//   out6 = x6 + g2*(A0+B5+b) + g4*(A4+B1+b) + g5*(A3+B2+b)
//
// Compute uses packed fma.rn.f32x2 over (even f, odd f) pairs so both the
// weight and the broadcast-x operand are natural LDS.64 loads; horizontal
// add at the end.  Each warp owns R=4 rows; lane handles z = lane, lane+32.
// ---------------------------------------------------------------------------

#define WSTRIDE 66              // floats per weight row in smem (64 + 2 pad)
#define RPW 4                   // rows per warp
#define WARPS 8
#define ROWS_PER_CTA (WARPS * RPW)   // 32
#define ROW 448                 // floats per batch row (7*64)

__device__ __forceinline__ void fma2(unsigned long long &acc,
                                     unsigned long long a,
                                     unsigned long long b) {
    asm("fma.rn.f32x2 %0, %1, %2, %0;" : "+l"(acc) : "l"(a), "l"(b));
}

__device__ __forceinline__ float accsum(unsigned long long a) {
    float lo = __uint_as_float((unsigned int)(a & 0xffffffffULL));
    float hi = __uint_as_float((unsigned int)(a >> 32));
    return lo + hi;
}

__global__ __launch_bounds__(256, 1)
void fano_kernel(const float* __restrict__ x, const float* __restrict__ W,
                 const float* __restrict__ bias, const float* __restrict__ gates,
                 float* __restrict__ out, int nrows)
{
    extern __shared__ float smem[];
    float* w1s = smem;                        // [64][WSTRIDE]
    float* w2s = w1s + 64 * WSTRIDE;          // [64][WSTRIDE]
    float* xs  = w2s + 64 * WSTRIDE;          // [ROWS_PER_CTA][ROW]

    const int tid = threadIdx.x;

    // --- stage weights: W[z][0:64] -> w1s, W[z][64:128] -> w2s -------------
    for (int i = tid; i < 64 * 128; i += 256) {
        int z = i >> 7, f = i & 127;
        float v = W[i];
        if (f < 64) w1s[z * WSTRIDE + f]        = v;
        else        w2s[z * WSTRIDE + (f - 64)] = v;
    }

    // --- stage x tile (32 rows, float4 coalesced) --------------------------
    long long rowbase  = (long long)blockIdx.x * ROWS_PER_CTA;
    long long elembase = rowbase * ROW;
    int tile_rows = (nrows - rowbase < ROWS_PER_CTA) ? (int)(nrows - rowbase)
                                                     : ROWS_PER_CTA;
    int tile_e4 = tile_rows * (ROW / 4);
    const float4* gx = reinterpret_cast<const float4*>(x + elembase);
    float4* sx = reinterpret_cast<float4*>(xs);
    for (int i = tid; i < tile_e4; i += 256) sx[i] = gx[i];

    __syncthreads();

    const int warp = tid >> 5, lane = tid & 31;
    const unsigned long long* w1u = reinterpret_cast<const unsigned long long*>(w1s);
    const unsigned long long* w2u = reinterpret_cast<const unsigned long long*>(w2s);
    const unsigned long long* xu  =
        reinterpret_cast<const unsigned long long*>(xs) + warp * RPW * (ROW / 2);

    // acc[r][res][zi]: res order A0 A1 A3 A4 B1 B2 B3 B5; zi 0 -> z=lane, 1 -> z=lane+32
    unsigned long long acc[RPW][8][2];
    #pragma unroll
    for (int r = 0; r < RPW; r++)
        #pragma unroll
        for (int j = 0; j < 8; j++) { acc[r][j][0] = 0ULL; acc[r][j][1] = 0ULL; }

    const int z0 = lane, z1 = lane + 32;
    const int w0off = z0 * (WSTRIDE / 2);     // ull index of w row for z0
    const int w1off = z1 * (WSTRIDE / 2);

    #pragma unroll 4
    for (int fp = 0; fp < 32; fp++) {          // f = 2*fp
        unsigned long long w1a = w1u[w0off + fp];
        unsigned long long w1b = w1u[w1off + fp];
        unsigned long long w2a = w2u[w0off + fp];
        unsigned long long w2b = w2u[w1off + fp];
        #pragma unroll
        for (int r = 0; r < RPW; r++) {
            const unsigned long long* xc = xu + r * (ROW / 2);
            unsigned long long x0 = xc[0 * 32 + fp];
            unsigned long long x1 = xc[1 * 32 + fp];
            unsigned long long x2 = xc[2 * 32 + fp];
            unsigned long long x3 = xc[3 * 32 + fp];
            unsigned long long x4 = xc[4 * 32 + fp];
            unsigned long long x5 = xc[5 * 32 + fp];
            fma2(acc[r][0][0], w1a, x0); fma2(acc[r][0][1], w1b, x0);  // A0
            fma2(acc[r][1][0], w1a, x1); fma2(acc[r][1][1], w1b, x1);  // A1
            fma2(acc[r][2][0], w1a, x3); fma2(acc[r][2][1], w1b, x3);  // A3
            fma2(acc[r][3][0], w1a, x4); fma2(acc[r][3][1], w1b, x4);  // A4
            fma2(acc[r][4][0], w2a, x1); fma2(acc[r][4][1], w2b, x1);  // B1
            fma2(acc[r][5][0], w2a, x2); fma2(acc[r][5][1], w2b, x2);  // B2
            fma2(acc[r][6][0], w2a, x3); fma2(acc[r][6][1], w2b, x3);  // B3
            fma2(acc[r][7][0], w2a, x5); fma2(acc[r][7][1], w2b, x5);  // B5
        }
    }

    // --- gates softmax (tiny, per-thread) ----------------------------------
    float graw[7];
    #pragma unroll
    for (int i = 0; i < 7; i++) graw[i] = gates[i];
    float m = graw[0];
    #pragma unroll
    for (int i = 1; i < 7; i++) m = fmaxf(m, graw[i]);
    float g[7], s = 0.f;
    #pragma unroll
    for (int i = 0; i < 7; i++) { g[i] = expf(graw[i] - m); s += g[i]; }
    float inv = 1.f / s;
    #pragma unroll
    for (int i = 0; i < 7; i++) g[i] *= inv;

    // --- epilogue: combine + write -----------------------------------------
    #pragma unroll
    for (int r = 0; r < RPW; r++) {
        long long row = rowbase + warp * RPW + r;
        if (row >= nrows) break;
        float* orow = out + row * (long long)ROW;
        const float* xrow = xs + (warp * RPW + r) * ROW;
        #pragma unroll
        for (int zi = 0; zi < 2; zi++) {
            int z = lane + zi * 32;
            float a0  = accsum(acc[r][0][zi]);
            float a1  = accsum(acc[r][1][zi]);
            float a3  = accsum(acc[r][2][zi]);
            float a4  = accsum(acc[r][3][zi]);
            float b1v = accsum(acc[r][4][zi]);
            float b2v = accsum(acc[r][5][zi]);
            float b3v = accsum(acc[r][6][zi]);
            float b5v = accsum(acc[r][7][zi]);
            float bz  = bias[z];
            orow[0 * 64 + z] = xrow[0 * 64 + z];
            orow[1 * 64 + z] = xrow[1 * 64 + z];
            orow[2 * 64 + z] = xrow[2 * 64 + z] + g[0] * (a0 + b1v + bz);
            orow[3 * 64 + z] = xrow[3 * 64 + z];
            orow[4 * 64 + z] = xrow[4 * 64 + z] + g[1] * (a0 + b3v + bz);
            orow[5 * 64 + z] = xrow[5 * 64 + z] + g[3] * (a1 + b3v + bz)
                                                + g[6] * (a4 + b2v + bz);
            orow[6 * 64 + z] = xrow[6 * 64 + z] + g[2] * (a0 + b5v + bz)
                                                + g[4] * (a4 + b1v + bz)
                                                + g[5] * (a3 + b2v + bz);
        }
    }
}

extern "C" void kernel_launch(void* const* d_in, const int* in_sizes, int n_in,
                              void* d_out, int out_size) {
    const float* x     = (const float*)d_in[0];   // colony_states [B,7,64]
    const float* W     = (const float*)d_in[1];   // [64,128]
    const float* bias  = (const float*)d_in[2];   // [64]
    const float* gates = (const float*)d_in[3];   // [7]
    float* out = (float*)d_out;

    int nrows = in_sizes[0] / ROW;
    int smem_bytes = (2 * 64 * WSTRIDE + ROWS_PER_CTA * ROW) * (int)sizeof(float);
    cudaFuncSetAttribute(fano_kernel,
                         cudaFuncAttributeMaxDynamicSharedMemorySize, smem_bytes);
    int ctas = (nrows + ROWS_PER_CTA - 1) / ROWS_PER_CTA;
    fano_kernel<<<ctas, 256, smem_bytes>>>(x, W, bias, gates, out, nrows);
}

// round 4
// speedup vs baseline: 1.1877x; 1.1877x over previous
#include <cuda_runtime.h>

// ---------------------------------------------------------------------------
// FanoCoupling: out = x + scatter-add over 7 Fano lines of softmax-gated
// Linear(concat(x_i, x_j)).
//
// Reduction: W = [W1 | W2], each 64x64.  Only 8 unique half-matvecs needed:
//   A0=W1 x0, A1=W1 x1, A3=W1 x3, A4=W1 x4, B1=W2 x1, B2=W2 x2, B3=W2 x3, B5=W2 x5
// Combine:
//   out0=x0, out1=x1, out3=x3
//   out2 = x2 + g0*(A0+B1+b)
//   out4 = x4 + g1*(A0+B3+b)
//   out5 = x5 + g3*(A1+B3+b) + g6*(A4+B2+b)
//   out6 = x6 + g2*(A0+B5+b) + g4*(A4+B1+b) + g5*(A3+B2+b)
//
// R3 changes vs R1: RPW 4->2 + launch_bounds(256,2) for 2 CTAs/SM (latency
// hiding), LDS.128 for weight rows (WSTRIDE=68 -> conflict-free phases) and
// for broadcast x, two f-pairs per inner iteration -> 80% FFMA2 issue density.
// ---------------------------------------------------------------------------

#define WSTRIDE 68              // floats per weight row in smem (16B-aligned rows)
#define RPW 2                   // rows per warp
#define WARPS 8
#define ROWS_PER_CTA (WARPS * RPW)   // 16
#define ROW 448                 // floats per batch row (7*64)

__device__ __forceinline__ void fma2(unsigned long long &acc,
                                     unsigned long long a,
                                     unsigned long long b) {
    asm("fma.rn.f32x2 %0, %1, %2, %0;" : "+l"(acc) : "l"(a), "l"(b));
}

__device__ __forceinline__ float accsum(unsigned long long a) {
    float lo = __uint_as_float((unsigned int)(a & 0xffffffffULL));
    float hi = __uint_as_float((unsigned int)(a >> 32));
    return lo + hi;
}

__global__ __launch_bounds__(256, 2)
void fano_kernel(const float* __restrict__ x, const float* __restrict__ W,
                 const float* __restrict__ bias, const float* __restrict__ gates,
                 float* __restrict__ out, int nrows)
{
    extern __shared__ float smem[];
    float* w1s = smem;                        // [64][WSTRIDE]
    float* w2s = w1s + 64 * WSTRIDE;          // [64][WSTRIDE]
    float* xs  = w2s + 64 * WSTRIDE;          // [ROWS_PER_CTA][ROW]

    const int tid = threadIdx.x;

    // --- stage weights: W[z][0:64] -> w1s, W[z][64:128] -> w2s -------------
    for (int i = tid; i < 64 * 128; i += 256) {
        int z = i >> 7, f = i & 127;
        float v = W[i];
        if (f < 64) w1s[z * WSTRIDE + f]        = v;
        else        w2s[z * WSTRIDE + (f - 64)] = v;
    }

    // --- stage x tile (16 rows, float4 coalesced) --------------------------
    long long rowbase  = (long long)blockIdx.x * ROWS_PER_CTA;
    long long elembase = rowbase * ROW;
    int tile_rows = (nrows - rowbase < ROWS_PER_CTA) ? (int)(nrows - rowbase)
                                                     : ROWS_PER_CTA;
    int tile_e4 = tile_rows * (ROW / 4);
    const float4* gx = reinterpret_cast<const float4*>(x + elembase);
    float4* sx = reinterpret_cast<float4*>(xs);
    for (int i = tid; i < tile_e4; i += 256) sx[i] = gx[i];

    __syncthreads();

    const int warp = tid >> 5, lane = tid & 31;
    const unsigned long long* w1u = reinterpret_cast<const unsigned long long*>(w1s);
    const unsigned long long* w2u = reinterpret_cast<const unsigned long long*>(w2s);
    const unsigned long long* xu  =
        reinterpret_cast<const unsigned long long*>(xs) + warp * RPW * (ROW / 2);

    // acc[r][res][zi]: res order A0 A1 A3 A4 B1 B2 B3 B5; zi 0 -> z=lane, 1 -> z=lane+32
    unsigned long long acc[RPW][8][2];
    #pragma unroll
    for (int r = 0; r < RPW; r++)
        #pragma unroll
        for (int j = 0; j < 8; j++) { acc[r][j][0] = 0ULL; acc[r][j][1] = 0ULL; }

    const int w0off = lane * (WSTRIDE / 2);          // ull index of w row for z=lane
    const int w1off = (lane + 32) * (WSTRIDE / 2);   // ... for z=lane+32

    #pragma unroll 4
    for (int fp2 = 0; fp2 < 16; fp2++) {       // covers f = 4*fp2 .. 4*fp2+3
        // weight pairs: .x -> f-pair (2*fp2), .y -> f-pair (2*fp2+1); LDS.128
        ulonglong2 w1a = *reinterpret_cast<const ulonglong2*>(w1u + w0off + 2 * fp2);
        ulonglong2 w1b = *reinterpret_cast<const ulonglong2*>(w1u + w1off + 2 * fp2);
        ulonglong2 w2a = *reinterpret_cast<const ulonglong2*>(w2u + w0off + 2 * fp2);
        ulonglong2 w2b = *reinterpret_cast<const ulonglong2*>(w2u + w1off + 2 * fp2);
        #pragma unroll
        for (int r = 0; r < RPW; r++) {
            const unsigned long long* xc = xu + r * (ROW / 2) + 2 * fp2;
            ulonglong2 x0 = *reinterpret_cast<const ulonglong2*>(xc + 0 * 32);
            ulonglong2 x1 = *reinterpret_cast<const ulonglong2*>(xc + 1 * 32);
            ulonglong2 x2 = *reinterpret_cast<const ulonglong2*>(xc + 2 * 32);
            ulonglong2 x3 = *reinterpret_cast<const ulonglong2*>(xc + 3 * 32);
            ulonglong2 x4 = *reinterpret_cast<const ulonglong2*>(xc + 4 * 32);
            ulonglong2 x5 = *reinterpret_cast<const ulonglong2*>(xc + 5 * 32);
            // f-pair even
            fma2(acc[r][0][0], w1a.x, x0.x); fma2(acc[r][0][1], w1b.x, x0.x);  // A0
            fma2(acc[r][1][0], w1a.x, x1.x); fma2(acc[r][1][1], w1b.x, x1.x);  // A1
            fma2(acc[r][2][0], w1a.x, x3.x); fma2(acc[r][2][1], w1b.x, x3.x);  // A3
            fma2(acc[r][3][0], w1a.x, x4.x); fma2(acc[r][3][1], w1b.x, x4.x);  // A4
            fma2(acc[r][4][0], w2a.x, x1.x); fma2(acc[r][4][1], w2b.x, x1.x);  // B1
            fma2(acc[r][5][0], w2a.x, x2.x); fma2(acc[r][5][1], w2b.x, x2.x);  // B2
            fma2(acc[r][6][0], w2a.x, x3.x); fma2(acc[r][6][1], w2b.x, x3.x);  // B3
            fma2(acc[r][7][0], w2a.x, x5.x); fma2(acc[r][7][1], w2b.x, x5.x);  // B5
            // f-pair odd
            fma2(acc[r][0][0], w1a.y, x0.y); fma2(acc[r][0][1], w1b.y, x0.y);
            fma2(acc[r][1][0], w1a.y, x1.y); fma2(acc[r][1][1], w1b.y, x1.y);
            fma2(acc[r][2][0], w1a.y, x3.y); fma2(acc[r][2][1], w1b.y, x3.y);
            fma2(acc[r][3][0], w1a.y, x4.y); fma2(acc[r][3][1], w1b.y, x4.y);
            fma2(acc[r][4][0], w2a.y, x1.y); fma2(acc[r][4][1], w2b.y, x1.y);
            fma2(acc[r][5][0], w2a.y, x2.y); fma2(acc[r][5][1], w2b.y, x2.y);
            fma2(acc[r][6][0], w2a.y, x3.y); fma2(acc[r][6][1], w2b.y, x3.y);
            fma2(acc[r][7][0], w2a.y, x5.y); fma2(acc[r][7][1], w2b.y, x5.y);
        }
    }

    // --- gates softmax (tiny, per-thread) ----------------------------------
    float graw[7];
    #pragma unroll
    for (int i = 0; i < 7; i++) graw[i] = gates[i];
    float m = graw[0];
    #pragma unroll
    for (int i = 1; i < 7; i++) m = fmaxf(m, graw[i]);
    float g[7], s = 0.f;
    #pragma unroll
    for (int i = 0; i < 7; i++) { g[i] = expf(graw[i] - m); s += g[i]; }
    float inv = 1.f / s;
    #pragma unroll
    for (int i = 0; i < 7; i++) g[i] *= inv;

    // --- epilogue: combine + write -----------------------------------------
    #pragma unroll
    for (int r = 0; r < RPW; r++) {
        long long row = rowbase + warp * RPW + r;
        if (row >= nrows) break;
        float* orow = out + row * (long long)ROW;
        const float* xrow = xs + (warp * RPW + r) * ROW;
        #pragma unroll
        for (int zi = 0; zi < 2; zi++) {
            int z = lane + zi * 32;
            float a0  = accsum(acc[r][0][zi]);
            float a1  = accsum(acc[r][1][zi]);
            float a3  = accsum(acc[r][2][zi]);
            float a4  = accsum(acc[r][3][zi]);
            float b1v = accsum(acc[r][4][zi]);
            float b2v = accsum(acc[r][5][zi]);
            float b3v = accsum(acc[r][6][zi]);
            float b5v = accsum(acc[r][7][zi]);
            float bz  = bias[z];
            orow[0 * 64 + z] = xrow[0 * 64 + z];
            orow[1 * 64 + z] = xrow[1 * 64 + z];
            orow[2 * 64 + z] = xrow[2 * 64 + z] + g[0] * (a0 + b1v + bz);
            orow[3 * 64 + z] = xrow[3 * 64 + z];
            orow[4 * 64 + z] = xrow[4 * 64 + z] + g[1] * (a0 + b3v + bz);
            orow[5 * 64 + z] = xrow[5 * 64 + z] + g[3] * (a1 + b3v + bz)
                                                + g[6] * (a4 + b2v + bz);
            orow[6 * 64 + z] = xrow[6 * 64 + z] + g[2] * (a0 + b5v + bz)
                                                + g[4] * (a4 + b1v + bz)
                                                + g[5] * (a3 + b2v + bz);
        }
    }
}

extern "C" void kernel_launch(void* const* d_in, const int* in_sizes, int n_in,
                              void* d_out, int out_size) {
    const float* x     = (const float*)d_in[0];   // colony_states [B,7,64]
    const float* W     = (const float*)d_in[1];   // [64,128]
    const float* bias  = (const float*)d_in[2];   // [64]
    const float* gates = (const float*)d_in[3];   // [7]
    float* out = (float*)d_out;

    int nrows = in_sizes[0] / ROW;
    int smem_bytes = (2 * 64 * WSTRIDE + ROWS_PER_CTA * ROW) * (int)sizeof(float);
    cudaFuncSetAttribute(fano_kernel,
                         cudaFuncAttributeMaxDynamicSharedMemorySize, smem_bytes);
    int ctas = (nrows + ROWS_PER_CTA - 1) / ROWS_PER_CTA;
    fano_kernel<<<ctas, 256, smem_bytes>>>(x, W, bias, gates, out, nrows);
}